// round 2
// baseline (speedup 1.0000x reference)
#include <cuda_runtime.h>
#include <cuda_bf16.h>

// Fused 3-block transformer encoder, one CTA per batch sample.
// B=4096, L=50, D=200, NUM_HEADS=1, NB=3. All fp32.
//
// Per block:
//   Q=relu(x Wq+bq), K=relu(x Wk+bk), V=relu(x Wv+bv)
//   scores = QK^T / sqrt(200); keys with sum(x_row)==0 -> NEG
//   attn = softmax(scores) * qmask;  x += attn V
//   t = relu(x W1 + b1); h = t W2 + b2
//   x = LN(h)*g + b + x

#define TL 50
#define TD 200
#define TNB 3
#define XS 204            // activation row stride (floats), 16B-aligned
#define SCS 52            // scores row stride
#define KC 8              // weight k-chunk rows staged in smem
#define NCHUNK 25         // 200 / 8
#define NEGV (-4294967295.0f)

// smem layout (floats)
#define OFF_XS   0
#define OFF_QS   (TL*XS)
#define OFF_KS   (2*TL*XS)
#define OFF_VS   (3*TL*XS)
#define OFF_SC   (4*TL*XS)
#define OFF_WB   (OFF_SC + TL*SCS)
#define OFF_BIAS (OFF_WB + KC*TD)
#define OFF_KM   (OFF_BIAS + 7*TD)
#define OFF_QM   (OFF_KM + TL)
#define OFF_TOK  (OFF_QM + TL)
#define SMEM_FLOATS (OFF_TOK + TL)
#define SMEM_BYTES  (SMEM_FLOATS * 4)

// ---------------------------------------------------------------------------
// GEMM: C[50,200] = act(A[50,200] @ W[200,200] + b)
// A, C in smem (stride XS). W in global (L2-resident), staged KC rows at a
// time into smem wb with register-prefetch overlap.
// Thread tile: 5 rows x 8 cols; tr = tid%10, tc = tid/10; tids >= 250 idle.
// ---------------------------------------------------------------------------
template<bool RELU>
__device__ __forceinline__ void gemm200(
    const float* __restrict__ A, const float* __restrict__ Wg,
    const float* __restrict__ bvec, float* __restrict__ Cdst,
    float* __restrict__ wb, int tid)
{
    const bool active = (tid < 250);
    const int tr = tid % 10;
    const int tc = tid / 10;
    const int r0 = active ? tr * 5 : 0;
    const int c0 = active ? tc * 8 : 0;

    float acc[5][8];
#pragma unroll
    for (int i = 0; i < 5; i++)
#pragma unroll
        for (int j = 0; j < 8; j++) acc[i][j] = 0.f;

    const bool l2 = (tid < 144);      // 400 float4 per chunk, 256 threads
    float4 p0, p1;
    {
        const float4* src = (const float4*)Wg;
        p0 = src[tid];
        if (l2) p1 = src[tid + 256];
    }

    for (int c = 0; c < NCHUNK; ++c) {
        __syncthreads();                       // wb free (prev chunk consumed)
        ((float4*)wb)[tid] = p0;
        if (l2) ((float4*)wb)[tid + 256] = p1;
        if (c + 1 < NCHUNK) {                  // prefetch next chunk (overlaps compute)
            const float4* src = (const float4*)(Wg + (c + 1) * KC * TD);
            p0 = src[tid];
            if (l2) p1 = src[tid + 256];
        }
        __syncthreads();

        const int kb = c * KC;
#pragma unroll
        for (int kk = 0; kk < KC; ++kk) {
            float xv[5];
#pragma unroll
            for (int i = 0; i < 5; i++) xv[i] = A[(r0 + i) * XS + kb + kk];
            float4 w0 = *(const float4*)(wb + kk * TD + c0);
            float4 w1 = *(const float4*)(wb + kk * TD + c0 + 4);
#pragma unroll
            for (int i = 0; i < 5; i++) {
                acc[i][0] = fmaf(xv[i], w0.x, acc[i][0]);
                acc[i][1] = fmaf(xv[i], w0.y, acc[i][1]);
                acc[i][2] = fmaf(xv[i], w0.z, acc[i][2]);
                acc[i][3] = fmaf(xv[i], w0.w, acc[i][3]);
                acc[i][4] = fmaf(xv[i], w1.x, acc[i][4]);
                acc[i][5] = fmaf(xv[i], w1.y, acc[i][5]);
                acc[i][6] = fmaf(xv[i], w1.z, acc[i][6]);
                acc[i][7] = fmaf(xv[i], w1.w, acc[i][7]);
            }
        }
    }

    if (active) {
#pragma unroll
        for (int i = 0; i < 5; i++)
#pragma unroll
            for (int j = 0; j < 8; j++) {
                float v = acc[i][j] + bvec[c0 + j];
                if (RELU) v = fmaxf(v, 0.f);
                Cdst[(r0 + i) * XS + c0 + j] = v;
            }
    }
}

__global__ __launch_bounds__(256, 1)
void xformer3_kernel(
    const int* __restrict__ tokens, const float* __restrict__ emb,
    const float* __restrict__ Wq, const float* __restrict__ bq,
    const float* __restrict__ Wk, const float* __restrict__ bk,
    const float* __restrict__ Wv, const float* __restrict__ bv,
    const float* __restrict__ W1, const float* __restrict__ b1,
    const float* __restrict__ W2, const float* __restrict__ b2,
    const float* __restrict__ lng, const float* __restrict__ lnb,
    float* __restrict__ out)
{
    extern __shared__ float sm[];
    float* xs   = sm + OFF_XS;
    float* qs   = sm + OFF_QS;
    float* ks   = sm + OFF_KS;
    float* vs   = sm + OFF_VS;
    float* sc   = sm + OFF_SC;
    float* wb   = sm + OFF_WB;
    float* bias = sm + OFF_BIAS;
    float* km   = sm + OFF_KM;
    float* qm   = sm + OFF_QM;
    int*   tok  = (int*)(sm + OFF_TOK);

    const int tid  = threadIdx.x;
    const int lane = tid & 31;
    const int wid  = tid >> 5;
    const int b    = blockIdx.x;

    // ---- token load + embedding gather ----
    if (tid < TL) tok[tid] = tokens[b * TL + tid];
    __syncthreads();
    for (int i = tid; i < TL * (TD / 4); i += 256) {
        int r = i / (TD / 4), c4 = i % (TD / 4);
        float4 v = *(const float4*)(emb + (size_t)tok[r] * TD + c4 * 4);
        *(float4*)(xs + r * XS + c4 * 4) = v;
    }
    __syncthreads();

    for (int blk = 0; blk < TNB; ++blk) {
        // ---- biases / LN params for this block into smem (explicit segments,
        //      no indexed pointer array -> no LMEM) ----
        {
            const int boff = blk * TD;
            for (int j = tid; j < TD; j += 256) {
                bias[0 * TD + j] = bq [boff + j];
                bias[1 * TD + j] = bk [boff + j];
                bias[2 * TD + j] = bv [boff + j];
                bias[3 * TD + j] = b1 [boff + j];
                bias[4 * TD + j] = b2 [boff + j];
                bias[5 * TD + j] = lng[boff + j];
                bias[6 * TD + j] = lnb[boff + j];
            }
        }
        // ---- key / query masks from current x (sum over D == 0) ----
        for (int r = wid; r < TL; r += 8) {
            float s = 0.f;
#pragma unroll
            for (int t = 0; t < 7; t++) {
                int c = lane + 32 * t;
                if (c < TD) s += xs[r * XS + c];
            }
#pragma unroll
            for (int o = 16; o; o >>= 1) s += __shfl_xor_sync(0xffffffffu, s, o);
            if (lane == 0) {
                float z = (s == 0.f) ? 1.f : 0.f;
                km[r] = z;
                qm[r] = 1.f - z;
            }
        }
        __syncthreads();

        // ---- Q, K, V ----
        gemm200<true>(xs, Wq + blk * TD * TD, bias + 0 * TD, qs, wb, tid);
        gemm200<true>(xs, Wk + blk * TD * TD, bias + 1 * TD, ks, wb, tid);
        gemm200<true>(xs, Wv + blk * TD * TD, bias + 2 * TD, vs, wb, tid);
        __syncthreads();

        // ---- scores = Q K^T * scale, key mask -> NEG ----
        if (tid < 250) {
            const int q0 = (tid % 10) * 5;
            const int k0 = (tid / 10) * 2;
            float acc[5][2];
#pragma unroll
            for (int i = 0; i < 5; i++) { acc[i][0] = 0.f; acc[i][1] = 0.f; }
            for (int d = 0; d < TD; d += 4) {
                float4 kv0 = *(const float4*)(ks + k0 * XS + d);
                float4 kv1 = *(const float4*)(ks + (k0 + 1) * XS + d);
#pragma unroll
                for (int i = 0; i < 5; i++) {
                    float4 qv = *(const float4*)(qs + (q0 + i) * XS + d);
                    acc[i][0] = fmaf(qv.x, kv0.x, acc[i][0]);
                    acc[i][0] = fmaf(qv.y, kv0.y, acc[i][0]);
                    acc[i][0] = fmaf(qv.z, kv0.z, acc[i][0]);
                    acc[i][0] = fmaf(qv.w, kv0.w, acc[i][0]);
                    acc[i][1] = fmaf(qv.x, kv1.x, acc[i][1]);
                    acc[i][1] = fmaf(qv.y, kv1.y, acc[i][1]);
                    acc[i][1] = fmaf(qv.z, kv1.z, acc[i][1]);
                    acc[i][1] = fmaf(qv.w, kv1.w, acc[i][1]);
                }
            }
            const float scale = 0.07071067811865475f;  // 1/sqrt(200)
#pragma unroll
            for (int i = 0; i < 5; i++)
#pragma unroll
                for (int j = 0; j < 2; j++) {
                    int kk = k0 + j;
                    float v = acc[i][j] * scale;
                    if (km[kk] != 0.f) v = NEGV;
                    sc[(q0 + i) * SCS + kk] = v;
                }
        }
        __syncthreads();

        // ---- softmax over keys (50), then * qmask ----
        for (int r = wid; r < TL; r += 8) {
            float* row = sc + r * SCS;
            float v0 = row[lane];
            float v1 = (lane < TL - 32) ? row[lane + 32] : -3.4e38f;
            float m = fmaxf(v0, v1);
#pragma unroll
            for (int o = 16; o; o >>= 1) m = fmaxf(m, __shfl_xor_sync(0xffffffffu, m, o));
            float e0 = __expf(v0 - m);
            float e1 = (lane < TL - 32) ? __expf(v1 - m) : 0.f;
            float s = e0 + e1;
#pragma unroll
            for (int o = 16; o; o >>= 1) s += __shfl_xor_sync(0xffffffffu, s, o);
            float f = qm[r] / s;
            row[lane] = e0 * f;
            if (lane < TL - 32) row[lane + 32] = e1 * f;
        }
        __syncthreads();

        // ---- x += attn @ V ----
        if (tid < 250) {
            const int r0 = (tid % 10) * 5;
            const int c0 = (tid / 10) * 8;
            float acc[5][8];
#pragma unroll
            for (int i = 0; i < 5; i++)
#pragma unroll
                for (int j = 0; j < 8; j++) acc[i][j] = 0.f;
#pragma unroll 5
            for (int k = 0; k < TL; k++) {
                float av[5];
#pragma unroll
                for (int i = 0; i < 5; i++) av[i] = sc[(r0 + i) * SCS + k];
                float4 v0 = *(const float4*)(vs + k * XS + c0);
                float4 v1 = *(const float4*)(vs + k * XS + c0 + 4);
#pragma unroll
                for (int i = 0; i < 5; i++) {
                    acc[i][0] = fmaf(av[i], v0.x, acc[i][0]);
                    acc[i][1] = fmaf(av[i], v0.y, acc[i][1]);
                    acc[i][2] = fmaf(av[i], v0.z, acc[i][2]);
                    acc[i][3] = fmaf(av[i], v0.w, acc[i][3]);
                    acc[i][4] = fmaf(av[i], v1.x, acc[i][4]);
                    acc[i][5] = fmaf(av[i], v1.y, acc[i][5]);
                    acc[i][6] = fmaf(av[i], v1.z, acc[i][6]);
                    acc[i][7] = fmaf(av[i], v1.w, acc[i][7]);
                }
            }
#pragma unroll
            for (int i = 0; i < 5; i++)
#pragma unroll
                for (int j = 0; j < 8; j++)
                    xs[(r0 + i) * XS + c0 + j] += acc[i][j];
        }
        __syncthreads();

        // ---- FFN: t = relu(x W1 + b1); h = t W2 + b2 ----
        gemm200<true >(xs, W1 + blk * TD * TD, bias + 3 * TD, qs, wb, tid);
        gemm200<false>(qs, W2 + blk * TD * TD, bias + 4 * TD, ks, wb, tid);
        __syncthreads();

        // ---- LayerNorm(h)*g + b + x -> x ----
        {
            const float* g  = bias + 5 * TD;
            const float* lb = bias + 6 * TD;
            for (int r = wid; r < TL; r += 8) {
                float xv[7];
                float s = 0.f;
#pragma unroll
                for (int t = 0; t < 7; t++) {
                    int c = lane + 32 * t;
                    xv[t] = (c < TD) ? ks[r * XS + c] : 0.f;
                    s += xv[t];
                }
#pragma unroll
                for (int o = 16; o; o >>= 1) s += __shfl_xor_sync(0xffffffffu, s, o);
                float mu = s * (1.f / TD);
                float s2 = 0.f;
#pragma unroll
                for (int t = 0; t < 7; t++) {
                    int c = lane + 32 * t;
                    float d = (c < TD) ? (xv[t] - mu) : 0.f;
                    s2 += d * d;
                }
#pragma unroll
                for (int o = 16; o; o >>= 1) s2 += __shfl_xor_sync(0xffffffffu, s2, o);
                float inv = rsqrtf(s2 * (1.f / TD) + 1e-8f);
#pragma unroll
                for (int t = 0; t < 7; t++) {
                    int c = lane + 32 * t;
                    if (c < TD) {
                        int idx = r * XS + c;
                        xs[idx] = (xv[t] - mu) * inv * g[c] + lb[c] + xs[idx];
                    }
                }
            }
        }
        __syncthreads();
    }

    // ---- store result ----
    for (int i = tid; i < TL * (TD / 4); i += 256) {
        int r = i / (TD / 4), c4 = i % (TD / 4);
        *(float4*)(out + (size_t)b * TL * TD + r * TD + c4 * 4) =
            *(const float4*)(xs + r * XS + c4 * 4);
    }
}

extern "C" void kernel_launch(void* const* d_in, const int* in_sizes, int n_in,
                              void* d_out, int out_size)
{
    const int*   tokens = (const int*)  d_in[0];
    const float* emb    = (const float*)d_in[1];
    const float* Wq     = (const float*)d_in[2];
    const float* bq     = (const float*)d_in[3];
    const float* Wk     = (const float*)d_in[4];
    const float* bk     = (const float*)d_in[5];
    const float* Wv     = (const float*)d_in[6];
    const float* bv     = (const float*)d_in[7];
    const float* W1     = (const float*)d_in[8];
    const float* b1     = (const float*)d_in[9];
    const float* W2     = (const float*)d_in[10];
    const float* b2     = (const float*)d_in[11];
    const float* lng    = (const float*)d_in[12];
    const float* lnb    = (const float*)d_in[13];
    float*       out    = (float*)d_out;

    const int B = in_sizes[0] / TL;

    cudaFuncSetAttribute(xformer3_kernel,
                         cudaFuncAttributeMaxDynamicSharedMemorySize, SMEM_BYTES);
    xformer3_kernel<<<B, 256, SMEM_BYTES>>>(
        tokens, emb, Wq, bq, Wk, bk, Wv, bv, W1, b1, W2, b2, lng, lnb, out);
}